// round 1
// baseline (speedup 1.0000x reference)
#include <cuda_runtime.h>
#include <cuda_fp16.h>
#include <stdint.h>

// Problem constants
#define B_   64
#define C_   2048
#define D_   512
#define M_   128
#define T_   100
#define NN_  1920
#define SPL  3          // splits of the non-muc rows per batch
#define RPS  640        // rows per split (NN_/SPL)
#define TN   32         // non rows per tile
#define NTILES 20       // RPS/TN

// Scratch (device globals; no allocation allowed)
__device__ __align__(16) __half g_nonH[(size_t)B_ * NN_ * D_];   // normalized non rows, fp16
__device__ __align__(16) __half g_mucH[(size_t)B_ * M_ * D_];    // normalized muc rows, fp16
__device__ __align__(16) float  g_mucN[(size_t)B_ * M_ * D_];    // normalized muc rows, fp32
__device__ float g_nonInv[B_ * NN_];
__device__ float g_partMax[B_ * SPL * M_];
__device__ int   g_partIdx[B_ * SPL * M_];
__device__ float g_trip[B_ * T_];

// ---------------------------------------------------------------------------
// Kernel 1: normalize + gather. One warp per (b, j) row of the gathered order:
// j < M_ -> muc list, else non list.
// ---------------------------------------------------------------------------
__global__ void __launch_bounds__(256) prep_kernel(const float* __restrict__ emb,
                                                   const int* __restrict__ muc_idx,
                                                   const int* __restrict__ non_idx) {
  int lane = threadIdx.x & 31;
  int r = blockIdx.x * 8 + (threadIdx.x >> 5);   // [0, B_*C_)
  int b = r >> 11;
  int j = r & 2047;
  int src, dstRow;
  bool isMuc = (j < M_);
  if (isMuc) { src = muc_idx[b * M_ + j]; dstRow = b * M_ + j; }
  else       { int jn = j - M_; src = non_idx[b * NN_ + jn]; dstRow = b * NN_ + jn; }

  const float4* p = (const float4*)(emb + ((size_t)b * C_ + src) * D_);
  float4 v[4];
  float ss = 0.f;
#pragma unroll
  for (int i = 0; i < 4; i++) {
    v[i] = p[lane + i * 32];
    ss += v[i].x * v[i].x + v[i].y * v[i].y + v[i].z * v[i].z + v[i].w * v[i].w;
  }
#pragma unroll
  for (int d = 16; d; d >>= 1) ss += __shfl_xor_sync(0xffffffffu, ss, d);
  float inv = 1.0f / fmaxf(sqrtf(ss), 1e-12f);

  if (isMuc) {
    float4* dn = (float4*)(g_mucN + (size_t)dstRow * D_);
    uint2*  dh = (uint2*)(g_mucH + (size_t)dstRow * D_);
#pragma unroll
    for (int i = 0; i < 4; i++) {
      float4 w = v[i];
      w.x *= inv; w.y *= inv; w.z *= inv; w.w *= inv;
      dn[lane + i * 32] = w;
      __half2 h0 = __floats2half2_rn(w.x, w.y);
      __half2 h1 = __floats2half2_rn(w.z, w.w);
      uint2 u; u.x = *(unsigned*)&h0; u.y = *(unsigned*)&h1;
      dh[lane + i * 32] = u;
    }
  } else {
    uint2* dh = (uint2*)(g_nonH + (size_t)dstRow * D_);
#pragma unroll
    for (int i = 0; i < 4; i++) {
      float4 w = v[i];
      w.x *= inv; w.y *= inv; w.z *= inv; w.w *= inv;
      __half2 h0 = __floats2half2_rn(w.x, w.y);
      __half2 h1 = __floats2half2_rn(w.z, w.w);
      uint2 u; u.x = *(unsigned*)&h0; u.y = *(unsigned*)&h1;
      dh[lane + i * 32] = u;
    }
    if (lane == 0) g_nonInv[dstRow] = inv;
  }
}

// ---------------------------------------------------------------------------
// Kernel 2: hard-negative mining GEMM + argmax.
// Block (s, b): 128 muc anchors (fp16, resident in smem) vs 640 non rows,
// streamed in 32-row double-buffered tiles via cp.async, mma.sync HMMA.
// ---------------------------------------------------------------------------
__device__ __forceinline__ uint32_t swz(uint32_t base, int row, int chunk) {
  // row stride = 1024B (512 halves); 16B chunks xor-swizzled by row%8
  return base + (uint32_t)(row << 10) + (uint32_t)(((chunk ^ (row & 7)) << 4));
}

__device__ __forceinline__ void cpasync16(uint32_t dst, const void* src) {
  asm volatile("cp.async.cg.shared.global [%0], [%1], 16;\n"
               :: "r"(dst), "l"(__cvta_generic_to_global(src)) : "memory");
}

__device__ __forceinline__ void ldsm4(uint32_t* r, uint32_t addr) {
  asm volatile("ldmatrix.sync.aligned.m8n8.x4.shared.b16 {%0,%1,%2,%3}, [%4];\n"
               : "=r"(r[0]), "=r"(r[1]), "=r"(r[2]), "=r"(r[3]) : "r"(addr));
}

__device__ __forceinline__ void mma16816(float* c, const uint32_t* a, uint32_t b0, uint32_t b1) {
  asm volatile("mma.sync.aligned.m16n8k16.row.col.f32.f16.f16.f32 "
               "{%0,%1,%2,%3}, {%4,%5,%6,%7}, {%8,%9}, {%0,%1,%2,%3};\n"
               : "+f"(c[0]), "+f"(c[1]), "+f"(c[2]), "+f"(c[3])
               : "r"(a[0]), "r"(a[1]), "r"(a[2]), "r"(a[3]), "r"(b0), "r"(b1));
}

__global__ void __launch_bounds__(256, 1) mine_kernel() {
  extern __shared__ char smem[];
  uint32_t sbase = (uint32_t)__cvta_generic_to_shared(smem);
  const uint32_t sA = sbase;                 // 128 x 512 half = 131072 B
  const uint32_t sBbase = sbase + 131072u;   // 2 x (32 x 512 half) = 2 x 32768 B

  int s = blockIdx.x, b = blockIdx.y;
  int tid = threadIdx.x, lane = tid & 31, w = tid >> 5;
  const __half* gA = g_mucH + (size_t)b * M_ * D_;
  const __half* gB = g_nonH + ((size_t)b * NN_ + (size_t)s * RPS) * D_;

  // Load anchors (group 0, together with tile 0)
#pragma unroll
  for (int i = 0; i < 32; i++) {
    int idx = tid + i * 256, row = idx >> 6, c = idx & 63;
    cpasync16(swz(sA, row, c), gA + (size_t)row * D_ + c * 8);
  }
#pragma unroll
  for (int i = 0; i < 8; i++) {
    int idx = tid + i * 256, row = idx >> 6, c = idx & 63;
    cpasync16(swz(sBbase, row, c), gB + (size_t)row * D_ + c * 8);
  }
  asm volatile("cp.async.commit_group;\n" ::: "memory");

  float bv0 = -1e30f, bv1 = -1e30f;
  int bi0 = 0, bi1 = 0;

  for (int tile = 0; tile < NTILES; tile++) {
    if (tile + 1 < NTILES) {
      const __half* gBn = gB + (size_t)(tile + 1) * TN * D_;
      uint32_t dstB = sBbase + (uint32_t)(((tile + 1) & 1) * 32768);
#pragma unroll
      for (int i = 0; i < 8; i++) {
        int idx = tid + i * 256, row = idx >> 6, c = idx & 63;
        cpasync16(swz(dstB, row, c), gBn + (size_t)row * D_ + c * 8);
      }
      asm volatile("cp.async.commit_group;\n" ::: "memory");
      asm volatile("cp.async.wait_group 1;\n" ::: "memory");
    } else {
      asm volatile("cp.async.wait_group 0;\n" ::: "memory");
    }
    __syncthreads();

    uint32_t sB = sBbase + (uint32_t)((tile & 1) * 32768);
    float acc[16];
#pragma unroll
    for (int i = 0; i < 16; i++) acc[i] = 0.f;

    int arow = w * 16 + (lane & 15);
    int brow = ((lane >> 4) << 3) + (lane & 7);
    int bsel = (lane >> 3) & 1;
#pragma unroll
    for (int ks = 0; ks < 32; ks++) {
      uint32_t a[4], bA[4], bB[4];
      ldsm4(a,  swz(sA, arow, ks * 2 + (lane >> 4)));
      ldsm4(bA, swz(sB, brow, ks * 2 + bsel));
      ldsm4(bB, swz(sB, brow + 16, ks * 2 + bsel));
      mma16816(acc + 0,  a, bA[0], bA[1]);   // n-tile 0 (cols 0..7)
      mma16816(acc + 4,  a, bA[2], bA[3]);   // n-tile 1 (cols 8..15)
      mma16816(acc + 8,  a, bB[0], bB[1]);   // n-tile 2 (cols 16..23)
      mma16816(acc + 12, a, bB[2], bB[3]);   // n-tile 3 (cols 24..31)
    }

    // Fold tile sims into running per-row argmax (first-occurrence tie-break)
    int colBase = s * RPS + tile * TN + ((lane & 3) << 1);
#pragma unroll
    for (int f = 0; f < 4; f++) {
      int c = colBase + f * 8;
      float v;
      v = acc[f * 4 + 0]; if (v > bv0 || (v == bv0 && c     < bi0)) { bv0 = v; bi0 = c; }
      v = acc[f * 4 + 1]; if (v > bv0 || (v == bv0 && c + 1 < bi0)) { bv0 = v; bi0 = c + 1; }
      v = acc[f * 4 + 2]; if (v > bv1 || (v == bv1 && c     < bi1)) { bv1 = v; bi1 = c; }
      v = acc[f * 4 + 3]; if (v > bv1 || (v == bv1 && c + 1 < bi1)) { bv1 = v; bi1 = c + 1; }
    }
    __syncthreads();   // protect buffer reuse by next prefetch
  }

  // Combine the 4 lanes that share each output row
#pragma unroll
  for (int d = 1; d < 4; d <<= 1) {
    float ov = __shfl_xor_sync(0xffffffffu, bv0, d);
    int   oi = __shfl_xor_sync(0xffffffffu, bi0, d);
    if (ov > bv0 || (ov == bv0 && oi < bi0)) { bv0 = ov; bi0 = oi; }
    ov = __shfl_xor_sync(0xffffffffu, bv1, d);
    oi = __shfl_xor_sync(0xffffffffu, bi1, d);
    if (ov > bv1 || (ov == bv1 && oi < bi1)) { bv1 = ov; bi1 = oi; }
  }
  if ((lane & 3) == 0) {
    int g = lane >> 2;
    int o = (b * SPL + s) * M_ + w * 16 + g;
    g_partMax[o] = bv0; g_partIdx[o] = bi0;
    g_partMax[o + 8] = bv1; g_partIdx[o + 8] = bi1;
  }
}

// ---------------------------------------------------------------------------
// Kernel 3: per-triplet loss. One warp per (b, t).
// ---------------------------------------------------------------------------
__global__ void __launch_bounds__(256) loss_kernel(const float* __restrict__ emb,
                                                   const int* __restrict__ non_idx,
                                                   const int* __restrict__ anchor_idx,
                                                   const int* __restrict__ pos_idx) {
  int lane = threadIdx.x & 31;
  int trip = blockIdx.x * 8 + (threadIdx.x >> 5);  // [0, B_*T_)
  int b = trip / T_, t = trip - b * T_;
  int a = anchor_idx[b * T_ + t];
  int p = pos_idx[b * T_ + t];

  float bv = -1e30f; int bi = 0;
#pragma unroll
  for (int sp = 0; sp < SPL; sp++) {
    int o = (b * SPL + sp) * M_ + a;
    float v = g_partMax[o]; int i2 = g_partIdx[o];
    if (v > bv || (v == bv && i2 < bi)) { bv = v; bi = i2; }
  }
  int cg = non_idx[b * NN_ + bi];
  float inv = g_nonInv[b * NN_ + bi];

  const float4* Ar = (const float4*)(g_mucN + ((size_t)b * M_ + a) * D_);
  const float4* Pr = (const float4*)(g_mucN + ((size_t)b * M_ + p) * D_);
  const float4* Nr = (const float4*)(emb + ((size_t)b * C_ + cg) * D_);
  float dp = 0.f, dn = 0.f;
#pragma unroll
  for (int i = 0; i < 4; i++) {
    float4 av = Ar[lane + i * 32], pv = Pr[lane + i * 32], nv = Nr[lane + i * 32];
    float e;
    e = av.x - pv.x + 1e-6f; dp += e * e;
    e = av.y - pv.y + 1e-6f; dp += e * e;
    e = av.z - pv.z + 1e-6f; dp += e * e;
    e = av.w - pv.w + 1e-6f; dp += e * e;
    e = av.x - nv.x * inv + 1e-6f; dn += e * e;
    e = av.y - nv.y * inv + 1e-6f; dn += e * e;
    e = av.z - nv.z * inv + 1e-6f; dn += e * e;
    e = av.w - nv.w * inv + 1e-6f; dn += e * e;
  }
#pragma unroll
  for (int d = 16; d; d >>= 1) {
    dp += __shfl_xor_sync(0xffffffffu, dp, d);
    dn += __shfl_xor_sync(0xffffffffu, dn, d);
  }
  if (lane == 0)
    g_trip[trip] = fmaxf(sqrtf(dp) - sqrtf(dn) + 1.0f, 0.0f);
}

// ---------------------------------------------------------------------------
// Kernel 4: deterministic final reduction.
// ---------------------------------------------------------------------------
__global__ void reduce_kernel(float* __restrict__ out) {
  __shared__ float sm[256];
  float s = 0.f;
  for (int i = threadIdx.x; i < B_ * T_; i += 256) s += g_trip[i];
  sm[threadIdx.x] = s;
  __syncthreads();
  for (int d = 128; d; d >>= 1) {
    if (threadIdx.x < d) sm[threadIdx.x] += sm[threadIdx.x + d];
    __syncthreads();
  }
  if (threadIdx.x == 0) out[0] = sm[0] * (1.0f / (float)(B_ * T_));
}

// ---------------------------------------------------------------------------
extern "C" void kernel_launch(void* const* d_in, const int* in_sizes, int n_in,
                              void* d_out, int out_size) {
  const float* emb = (const float*)d_in[0];
  const int* muc = (const int*)d_in[1];
  const int* non = (const int*)d_in[2];
  const int* anc = (const int*)d_in[3];
  const int* pos = (const int*)d_in[4];

  cudaFuncSetAttribute(mine_kernel, cudaFuncAttributeMaxDynamicSharedMemorySize, 196608);

  prep_kernel<<<(B_ * C_) / 8, 256>>>(emb, muc, non);
  mine_kernel<<<dim3(SPL, B_), 256, 196608>>>();
  loss_kernel<<<(B_ * T_) / 8, 256>>>(emb, non, anc, pos);
  reduce_kernel<<<1, 256>>>((float*)d_out);
}